// round 5
// baseline (speedup 1.0000x reference)
#include <cuda_runtime.h>
#include <cuda_bf16.h>
#include <cuda_fp16.h>
#include <cstdint>

#define F_DIM 300
#define KPAD 320           // 5 k-chunks of 64
#define NPAD 384
#define MAX_NLAST 100000
#define MAX_NCUR  50000
#define MAX_E     500000

// ---------------- scratch (static __device__; no allocation) ----------------
__device__ __half d_PC[(size_t)MAX_NLAST * F_DIM];     // fp16: 60MB, L2-resident for seg
__device__ float d_c2[(size_t)MAX_NCUR * F_DIM];
__device__ float d_aggmax[(size_t)MAX_NCUR * F_DIM];
__device__ float d_aggmin[(size_t)MAX_NCUR * F_DIM];
__device__ float d_ypre[(size_t)MAX_NCUR * F_DIM];
__device__ __nv_bfloat16 d_W1hi[(size_t)NPAD * KPAD];
__device__ __nv_bfloat16 d_W1lo[(size_t)NPAD * KPAD];
__device__ __nv_bfloat16 d_W2hi[(size_t)NPAD * KPAD];
__device__ __nv_bfloat16 d_W2lo[(size_t)NPAD * KPAD];
__device__ int   d_counts[MAX_NCUR];
__device__ int   d_offsets[MAX_NCUR];
__device__ int   d_cursor[MAX_NCUR];
__device__ int   d_edge_l[MAX_E];
__device__ float d_colsum1[F_DIM], d_colsq1[F_DIM];
__device__ float d_colsum2[F_DIM], d_colsq2[F_DIM];
__device__ float d_scale1[F_DIM], d_shift1[F_DIM];
__device__ float d_scale2[F_DIM], d_shift2[F_DIM];

// ---------------- PTX helpers (baseline sm_80+) ----------------
static __device__ __forceinline__ uint32_t smem_u32(const void* p) {
    uint32_t a;
    asm("{ .reg .u64 t; cvta.to.shared.u64 t, %1; cvt.u32.u64 %0, t; }" : "=r"(a) : "l"(p));
    return a;
}
static __device__ __forceinline__ void cp16(uint32_t dst, const void* src, bool pred) {
    int sz = pred ? 16 : 0;
    asm volatile("cp.async.cg.shared.global [%0], [%1], 16, %2;" :: "r"(dst), "l"(src), "r"(sz));
}
#define CP_COMMIT() asm volatile("cp.async.commit_group;" ::: "memory")
#define CP_WAIT(n)  asm volatile("cp.async.wait_group %0;" :: "n"(n) : "memory")

static __device__ __forceinline__ void ldsm_x4(uint32_t* r, uint32_t addr) {
    asm volatile("ldmatrix.sync.aligned.m8n8.x4.shared.b16 {%0,%1,%2,%3}, [%4];"
        : "=r"(r[0]), "=r"(r[1]), "=r"(r[2]), "=r"(r[3]) : "r"(addr));
}
static __device__ __forceinline__ void mma_bf16(float* d, const uint32_t* a, const uint32_t* b) {
    asm volatile("mma.sync.aligned.m16n8k16.row.col.f32.bf16.bf16.f32 "
        "{%0,%1,%2,%3}, {%4,%5,%6,%7}, {%8,%9}, {%0,%1,%2,%3};"
        : "+f"(d[0]), "+f"(d[1]), "+f"(d[2]), "+f"(d[3])
        : "r"(a[0]), "r"(a[1]), "r"(a[2]), "r"(a[3]), "r"(b[0]), "r"(b[1]));
}

// ---------------- fused GEMM ----------------
// smem layout (bytes):
#define GSM_P   0               // fp32 primary src, 2 stages x 32768
#define GSM_Q   65536           // fp32 secondary (min) src, 2 stages x 32768 (MODE 1)
#define GSM_B   131072          // per stage: Bhi 16384 + Blo 16384; 2 stages
#define GSM_AH  196608          // bf16 A-hi tile 16384
#define GSM_AL  212992          // bf16 A-lo tile 16384
#define GSM_SC  229376          // 320 floats
#define GSM_SH  230656          // 320 floats
#define GSM_TOTAL 231936

// MODE 0: C(half PC) = concat(P0=feat, P1=coor) @ Wt + bias           (GEMM1)
// MODE 1: C(float ypre) = relu(BN1sel(P0=aggmax,P1=aggmin) @ Wt + bias), + col stats  (GEMM2)
// NP: n8-tile pairs per warp (4 => block covers 128 cols; 2 => 64 cols)
template<int NP, int MODE>
__global__ __launch_bounds__(128, 1)
void mma_fused(const float* __restrict__ P0, const float* __restrict__ P1,
               const __nv_bfloat16* __restrict__ Bhi, const __nv_bfloat16* __restrict__ Blo,
               int M, int noff_base,
               const float* __restrict__ scale, const float* __restrict__ shift,
               const float* __restrict__ bias, void* __restrict__ Cout,
               float* __restrict__ colsum, float* __restrict__ colsq)
{
    extern __shared__ __align__(128) char smem[];
    const uint32_t sb = smem_u32(smem);
    const int tid = threadIdx.x, wid = tid >> 5, lane = tid & 31;
    const int wm = wid & 1, wn = wid >> 1;
    const int m0 = blockIdx.x * 128;
    const int noff = noff_base + blockIdx.y * 128;

    float* sc_s = (float*)(smem + GSM_SC);
    float* sh_s = (float*)(smem + GSM_SH);
    if (MODE == 1) {
        for (int i = tid; i < KPAD; i += 128) {
            sc_s[i] = (i < F_DIM) ? scale[i] : 0.f;
            sh_s[i] = (i < F_DIM) ? shift[i] : 0.f;
        }
    }

    auto load_chunk = [&](int cc) {
        const int st = cc & 1;
        const int k0 = cc * 64;
#pragma unroll
        for (int i = 0; i < 16; i++) {               // fp32 A: 128 rows x 16 groups of 16B
            int lin = i * 128 + tid;
            int row = lin >> 4, g = lin & 15;
            int kg = k0 + g * 4;
            bool ok = ((m0 + row) < M) && (kg < F_DIM);
            size_t so = ok ? ((size_t)(m0 + row) * F_DIM + kg) : 0;
            uint32_t ao = st * 32768 + row * 256 + ((g ^ (row & 7)) * 16);
            cp16(sb + GSM_P + ao, P0 + so, ok);
            if (MODE == 1) cp16(sb + GSM_Q + ao, P1 + so, ok);
        }
#pragma unroll
        for (int i = 0; i < 8; i++) {                // B tiles: 128 rows x 8 chunks
            int lin = i * 128 + tid;
            int row = lin >> 3, c = lin & 7;
            size_t so = (size_t)(noff + row) * KPAD + k0 + c * 8;
            uint32_t bo = st * 32768 + row * 128 + ((c ^ (row & 7)) * 16);
            cp16(sb + GSM_B + bo, Bhi + so, true);
            cp16(sb + GSM_B + 16384 + bo, Blo + so, true);
        }
        CP_COMMIT();
    };

    float acc[4][2 * NP][4];
#pragma unroll
    for (int mt = 0; mt < 4; mt++)
#pragma unroll
        for (int nt = 0; nt < 2 * NP; nt++)
#pragma unroll
            for (int q = 0; q < 4; q++) acc[mt][nt][q] = 0.f;

    load_chunk(0);

    for (int cc = 0; cc < 5; cc++) {
        if (cc < 4) { load_chunk(cc + 1); CP_WAIT(1); }
        else        { CP_WAIT(0); }
        __syncthreads();
        const int st = cc & 1;
        const int k0 = cc * 64;

        if (MODE == 0 && cc == 4) {                  // patch coor cols 300..302 (group g=11)
            int row = tid;
            if (m0 + row < M) {
                const float* cp_ = P1 + (size_t)(m0 + row) * 3;
                *(float4*)(smem + GSM_P + st * 32768 + row * 256 + ((11 ^ (row & 7)) * 16))
                    = make_float4(cp_[0], cp_[1], cp_[2], 0.f);
            }
            __syncthreads();
        }

        // convert fp32 -> bf16 hi/lo swizzled tiles
#pragma unroll
        for (int i = 0; i < 8; i++) {
            int lin = i * 128 + tid;
            int row = lin >> 3, ch = lin & 7;
            const char* pb = smem + GSM_P + st * 32768 + row * 256;
            float4 f0 = *(const float4*)(pb + (((2 * ch) ^ (row & 7)) * 16));
            float4 f1 = *(const float4*)(pb + (((2 * ch + 1) ^ (row & 7)) * 16));
            float v[8] = {f0.x, f0.y, f0.z, f0.w, f1.x, f1.y, f1.z, f1.w};
            if (MODE == 1) {
                const char* qb = smem + GSM_Q + st * 32768 + row * 256;
                float4 q0 = *(const float4*)(qb + (((2 * ch) ^ (row & 7)) * 16));
                float4 q1 = *(const float4*)(qb + (((2 * ch + 1) ^ (row & 7)) * 16));
                float qv[8] = {q0.x, q0.y, q0.z, q0.w, q1.x, q1.y, q1.z, q1.w};
                int kb = k0 + ch * 8;
                float4 sa = *(const float4*)&sc_s[kb], sb2 = *(const float4*)&sc_s[kb + 4];
                float4 ha = *(const float4*)&sh_s[kb], hb2 = *(const float4*)&sh_s[kb + 4];
                float scv[8] = {sa.x, sa.y, sa.z, sa.w, sb2.x, sb2.y, sb2.z, sb2.w};
                float shv[8] = {ha.x, ha.y, ha.z, ha.w, hb2.x, hb2.y, hb2.z, hb2.w};
#pragma unroll
                for (int j = 0; j < 8; j++) {
                    float m_ = v[j], r_ = 0.f;
                    if (m_ >= 0.f) {
                        float sc = scv[j];
                        float b_ = (sc >= 0.f) ? m_ : qv[j];
                        r_ = fmaf(b_, sc, shv[j]);
                    }
                    v[j] = r_;
                }
            }
            uint32_t hp[4], lp[4];
#pragma unroll
            for (int j = 0; j < 4; j++) {
                __nv_bfloat16 h0 = __float2bfloat16(v[2 * j]);
                __nv_bfloat16 h1 = __float2bfloat16(v[2 * j + 1]);
                __nv_bfloat162 hh = __halves2bfloat162(h0, h1);
                hp[j] = *(uint32_t*)&hh;
                __nv_bfloat162 ll = __floats2bfloat162_rn(
                    v[2 * j] - __bfloat162float(h0), v[2 * j + 1] - __bfloat162float(h1));
                lp[j] = *(uint32_t*)&ll;
            }
            uint32_t ao = row * 128 + ((ch ^ (row & 7)) * 16);
            *(uint4*)(smem + GSM_AH + ao) = make_uint4(hp[0], hp[1], hp[2], hp[3]);
            *(uint4*)(smem + GSM_AL + ao) = make_uint4(lp[0], lp[1], lp[2], lp[3]);
        }
        __syncthreads();

        // MMA: 3 products over this k-chunk
#pragma unroll
        for (int p = 0; p < 3; p++) {
            const uint32_t Ab = sb + ((p == 2) ? GSM_AL : GSM_AH);
            const uint32_t Bb = sb + GSM_B + st * 32768 + ((p == 1) ? 16384 : 0);
#pragma unroll
            for (int kk = 0; kk < 4; kk++) {
                uint32_t af[4][4], bf[2 * NP][2];
#pragma unroll
                for (int mt = 0; mt < 4; mt++) {
                    int row = wm * 64 + mt * 16 + (lane & 15);
                    int c = kk * 2 + (lane >> 4);
                    ldsm_x4(af[mt], Ab + row * 128 + ((c ^ (row & 7)) * 16));
                }
#pragma unroll
                for (int np = 0; np < NP; np++) {
                    int row = wn * (NP * 16) + np * 16 + ((lane >> 4) << 3) + (lane & 7);
                    int c = kk * 2 + ((lane >> 3) & 1);
                    uint32_t r4[4];
                    ldsm_x4(r4, Bb + row * 128 + ((c ^ (row & 7)) * 16));
                    bf[np * 2][0] = r4[0]; bf[np * 2][1] = r4[1];
                    bf[np * 2 + 1][0] = r4[2]; bf[np * 2 + 1][1] = r4[3];
                }
#pragma unroll
                for (int mt = 0; mt < 4; mt++)
#pragma unroll
                    for (int nt = 0; nt < 2 * NP; nt++)
                        mma_bf16(acc[mt][nt], af[mt], bf[nt]);
            }
        }
        __syncthreads();
    }

    // ---- epilogue ----
    const int g = lane >> 2, t4 = lane & 3;
    const int c0 = noff + wn * (NP * 16);

    if (MODE == 0) {
        __half* PC = (__half*)Cout;
#pragma unroll
        for (int mt = 0; mt < 4; mt++)
#pragma unroll
            for (int hf = 0; hf < 2; hf++) {
                const int row = m0 + wm * 64 + mt * 16 + g + hf * 8;
                if (row < M) {
#pragma unroll
                    for (int nt = 0; nt < 2 * NP; nt++) {
                        const int col = c0 + nt * 8 + 2 * t4;
                        if (col + 1 < F_DIM) {
                            const float2 bv = *(const float2*)(bias + col);
                            float v0 = acc[mt][nt][hf * 2] + bv.x;
                            float v1 = acc[mt][nt][hf * 2 + 1] + bv.y;
                            *(__half2*)(PC + (size_t)row * F_DIM + col) = __floats2half2_rn(v0, v1);
                        }
                    }
                }
            }
    } else {
        float* Y = (float*)Cout;
        float cs[2 * NP][2], cq[2 * NP][2];
#pragma unroll
        for (int nt = 0; nt < 2 * NP; nt++) { cs[nt][0] = cs[nt][1] = 0.f; cq[nt][0] = cq[nt][1] = 0.f; }
#pragma unroll
        for (int mt = 0; mt < 4; mt++)
#pragma unroll
            for (int hf = 0; hf < 2; hf++) {
                const int row = m0 + wm * 64 + mt * 16 + g + hf * 8;
                if (row < M) {
#pragma unroll
                    for (int nt = 0; nt < 2 * NP; nt++) {
                        const int col = c0 + nt * 8 + 2 * t4;
                        if (col + 1 < F_DIM) {
                            const float2 bv = *(const float2*)(bias + col);
                            float v0 = fmaxf(acc[mt][nt][hf * 2] + bv.x, 0.f);
                            float v1 = fmaxf(acc[mt][nt][hf * 2 + 1] + bv.y, 0.f);
                            *(float2*)(Y + (size_t)row * F_DIM + col) = make_float2(v0, v1);
                            cs[nt][0] += v0; cq[nt][0] += v0 * v0;
                            cs[nt][1] += v1; cq[nt][1] += v1 * v1;
                        }
                    }
                }
            }
        __syncthreads();
        float* redS = (float*)smem;
        float* redQ = (float*)smem + NP * 32;
        if (tid < NP * 32) { redS[tid] = 0.f; redQ[tid] = 0.f; }
        __syncthreads();
#pragma unroll
        for (int nt = 0; nt < 2 * NP; nt++) {
            int lc = wn * (NP * 16) + nt * 8 + 2 * t4;
            atomicAdd(&redS[lc], cs[nt][0]);     atomicAdd(&redQ[lc], cq[nt][0]);
            atomicAdd(&redS[lc + 1], cs[nt][1]); atomicAdd(&redQ[lc + 1], cq[nt][1]);
        }
        __syncthreads();
        if (tid < NP * 32) {
            int col = noff + tid;
            if (col < F_DIM) {
                atomicAdd(colsum + col, redS[tid]);
                atomicAdd(colsq + col, redQ[tid]);
            }
        }
    }
}

// ---------------- W split conversion ----------------
__global__ void convW_kernel(const float* __restrict__ W, int Krows,
                             __nv_bfloat16* __restrict__ hi, __nv_bfloat16* __restrict__ lo) {
    int idx = blockIdx.x * blockDim.x + threadIdx.x;
    if (idx >= NPAD * (KPAD / 2)) return;
    int n = idx / (KPAD / 2), k = (idx % (KPAD / 2)) * 2;
    float v0 = (n < F_DIM && k < Krows) ? W[(size_t)k * F_DIM + n] : 0.f;
    float v1 = (n < F_DIM && k + 1 < Krows) ? W[(size_t)(k + 1) * F_DIM + n] : 0.f;
    __nv_bfloat16 h0 = __float2bfloat16(v0), h1 = __float2bfloat16(v1);
    __nv_bfloat162 hh = __halves2bfloat162(h0, h1);
    __nv_bfloat162 ll = __floats2bfloat162_rn(v0 - __bfloat162float(h0), v1 - __bfloat162float(h1));
    *(uint32_t*)(hi + (size_t)n * KPAD + k) = *(uint32_t*)&hh;
    *(uint32_t*)(lo + (size_t)n * KPAD + k) = *(uint32_t*)&ll;
}

// ---------------- graph/CSR + misc ----------------
__global__ void reset_kernel(int ncur) {
    int i = blockIdx.x * blockDim.x + threadIdx.x;
    if (i < ncur) d_counts[i] = 0;
    if (i < F_DIM) {
        d_colsum1[i] = 0.f; d_colsq1[i] = 0.f;
        d_colsum2[i] = 0.f; d_colsq2[i] = 0.f;
    }
}

__global__ void c2_kernel(const float* __restrict__ ccoors, const float* __restrict__ W1, int ncur) {
    int idx = blockIdx.x * blockDim.x + threadIdx.x;
    if (idx >= ncur * F_DIM) return;
    int i = idx / F_DIM, c = idx % F_DIM;
    float x = ccoors[3 * i], y = ccoors[3 * i + 1], z = ccoors[3 * i + 2];
    d_c2[idx] = x * W1[(size_t)300 * F_DIM + c]
              + y * W1[(size_t)301 * F_DIM + c]
              + z * W1[(size_t)302 * F_DIM + c];
}

__global__ void count_kernel(const int* __restrict__ cur_idx, int E) {
    int e = blockIdx.x * blockDim.x + threadIdx.x;
    if (e < E) atomicAdd(&d_counts[cur_idx[e]], 1);
}

__global__ void scan_kernel(int n) {
    __shared__ int buf[1024];
    __shared__ int carry_s;
    int tid = threadIdx.x;
    if (tid == 0) carry_s = 0;
    __syncthreads();
    for (int base = 0; base < n; base += 1024) {
        int i = base + tid;
        int x = (i < n) ? d_counts[i] : 0;
        buf[tid] = x;
        __syncthreads();
        for (int off = 1; off < 1024; off <<= 1) {
            int v = (tid >= off) ? buf[tid - off] : 0;
            __syncthreads();
            buf[tid] += v;
            __syncthreads();
        }
        int carry = carry_s;
        int excl = carry + buf[tid] - x;
        if (i < n) { d_offsets[i] = excl; d_cursor[i] = excl; }
        __syncthreads();
        if (tid == 1023) carry_s = carry + buf[1023];
        __syncthreads();
    }
}

__global__ void scatter_kernel(const int* __restrict__ cur_idx, const int* __restrict__ last_idx, int E) {
    int e = blockIdx.x * blockDim.x + threadIdx.x;
    if (e < E) {
        int p = atomicAdd(&d_cursor[cur_idx[e]], 1);
        d_edge_l[p] = last_idx[e];
    }
}

// per-segment max/min of relu(PC[l]-c2[i]) + BN1 stats; PC is fp16 (half2 loads)
#define SEGS_PER_BLOCK 4
__global__ __launch_bounds__(128) void seg_kernel(int ncur) {
    const int tid = threadIdx.x;
    const bool h2 = (tid < 22);                 // pairs 128..149 -> cols 256..299
    float2 s0 = {0.f, 0.f}, q0 = {0.f, 0.f}, s1 = {0.f, 0.f}, q1 = {0.f, 0.f};

    int segBeg = blockIdx.x * SEGS_PER_BLOCK;
    int segEnd = min(segBeg + SEGS_PER_BLOCK, ncur);
    for (int seg = segBeg; seg < segEnd; seg++) {
        const float2* c2r = (const float2*)(d_c2 + (size_t)seg * F_DIM);
        float2 cA = c2r[tid];
        float2 cB = h2 ? c2r[128 + tid] : make_float2(0.f, 0.f);
        float2 mxA = {-1.f, -1.f}, mxB = {-1.f, -1.f};
        float2 mnA = {3.4e38f, 3.4e38f}, mnB = {3.4e38f, 3.4e38f};
        int off = d_offsets[seg], cnt = d_counts[seg];
        int t = 0;
        for (; t + 4 <= cnt; t += 4) {
            int l[4];
#pragma unroll
            for (int u = 0; u < 4; u++) l[u] = d_edge_l[off + t + u];
            float2 va[4], vb[4];
#pragma unroll
            for (int u = 0; u < 4; u++) {
                const __half2* pr = (const __half2*)(d_PC + (size_t)l[u] * F_DIM);
                va[u] = __half22float2(pr[tid]);
                vb[u] = h2 ? __half22float2(pr[128 + tid]) : make_float2(0.f, 0.f);
            }
#pragma unroll
            for (int u = 0; u < 4; u++) {
                float ax = fmaxf(va[u].x - cA.x, 0.f), ay = fmaxf(va[u].y - cA.y, 0.f);
                float bx = fmaxf(vb[u].x - cB.x, 0.f), by = fmaxf(vb[u].y - cB.y, 0.f);
                s0.x += ax; q0.x += ax * ax; mxA.x = fmaxf(mxA.x, ax); mnA.x = fminf(mnA.x, ax);
                s0.y += ay; q0.y += ay * ay; mxA.y = fmaxf(mxA.y, ay); mnA.y = fminf(mnA.y, ay);
                s1.x += bx; q1.x += bx * bx; mxB.x = fmaxf(mxB.x, bx); mnB.x = fminf(mnB.x, bx);
                s1.y += by; q1.y += by * by; mxB.y = fmaxf(mxB.y, by); mnB.y = fminf(mnB.y, by);
            }
        }
        for (; t < cnt; t++) {
            int lv = d_edge_l[off + t];
            const __half2* pr = (const __half2*)(d_PC + (size_t)lv * F_DIM);
            float2 va = __half22float2(pr[tid]);
            float2 vb = h2 ? __half22float2(pr[128 + tid]) : make_float2(0.f, 0.f);
            float ax = fmaxf(va.x - cA.x, 0.f), ay = fmaxf(va.y - cA.y, 0.f);
            float bx = fmaxf(vb.x - cB.x, 0.f), by = fmaxf(vb.y - cB.y, 0.f);
            s0.x += ax; q0.x += ax * ax; mxA.x = fmaxf(mxA.x, ax); mnA.x = fminf(mnA.x, ax);
            s0.y += ay; q0.y += ay * ay; mxA.y = fmaxf(mxA.y, ay); mnA.y = fminf(mnA.y, ay);
            s1.x += bx; q1.x += bx * bx; mxB.x = fmaxf(mxB.x, bx); mnB.x = fminf(mnB.x, bx);
            s1.y += by; q1.y += by * by; mxB.y = fmaxf(mxB.y, by); mnB.y = fminf(mnB.y, by);
        }
        size_t base = (size_t)seg * F_DIM;
        *(float2*)(d_aggmax + base + 2 * tid) = mxA;
        *(float2*)(d_aggmin + base + 2 * tid) =
            cnt ? mnA : make_float2(0.f, 0.f);
        if (h2) {
            *(float2*)(d_aggmax + base + 256 + 2 * tid) = mxB;
            *(float2*)(d_aggmin + base + 256 + 2 * tid) =
                cnt ? mnB : make_float2(0.f, 0.f);
        }
    }
    atomicAdd(&d_colsum1[2 * tid], s0.x);     atomicAdd(&d_colsq1[2 * tid], q0.x);
    atomicAdd(&d_colsum1[2 * tid + 1], s0.y); atomicAdd(&d_colsq1[2 * tid + 1], q0.y);
    if (h2) {
        atomicAdd(&d_colsum1[256 + 2 * tid], s1.x);     atomicAdd(&d_colsq1[256 + 2 * tid], q1.x);
        atomicAdd(&d_colsum1[257 + 2 * tid], s1.y);     atomicAdd(&d_colsq1[257 + 2 * tid], q1.y);
    }
}

__global__ void bnparam_kernel(const float* __restrict__ colsum, const float* __restrict__ colsq,
                               float invN, const float* __restrict__ g, const float* __restrict__ be,
                               float* __restrict__ scale, float* __restrict__ shift) {
    int c = blockIdx.x * blockDim.x + threadIdx.x;
    if (c >= F_DIM) return;
    float mean = colsum[c] * invN;
    float var = colsq[c] * invN - mean * mean;
    if (var < 0.f) var = 0.f;
    float sc = g[c] * rsqrtf(var + 1e-5f);
    scale[c] = sc;
    shift[c] = be[c] - mean * sc;
}

__global__ void apply_out_kernel(float* __restrict__ out, int ncur) {
    int idx = blockIdx.x * blockDim.x + threadIdx.x;
    if (idx >= ncur * F_DIM) return;
    int c = idx % F_DIM;
    out[idx] = fmaf(d_ypre[idx], d_scale2[c], d_shift2[c]);
}

// ---------------- launcher ----------------
extern "C" void kernel_launch(void* const* d_in, const int* in_sizes, int n_in,
                              void* d_out, int out_size) {
    const float* last_coors    = (const float*)d_in[0];
    const float* last_features = (const float*)d_in[1];
    const float* current_coors = (const float*)d_in[2];
    const int*   cur_idx       = (const int*)d_in[3];
    const int*   last_idx      = (const int*)d_in[4];
    const float* W1            = (const float*)d_in[5];
    const float* b1            = (const float*)d_in[6];
    const float* g1            = (const float*)d_in[7];
    const float* be1           = (const float*)d_in[8];
    const float* W2            = (const float*)d_in[9];
    const float* b2            = (const float*)d_in[10];
    const float* g2            = (const float*)d_in[11];
    const float* be2           = (const float*)d_in[12];

    const int Nlast = in_sizes[0] / 3;
    const int Ncur  = in_sizes[2] / 3;
    const int E     = in_sizes[3];

    __half* pPC;
    float *pYpre, *pAmax, *pAmin, *pSum1, *pSq1, *pSum2, *pSq2, *pSc1, *pSh1, *pSc2, *pSh2;
    __nv_bfloat16 *pW1h, *pW1l, *pW2h, *pW2l;
    cudaGetSymbolAddress((void**)&pPC,   d_PC);
    cudaGetSymbolAddress((void**)&pYpre, d_ypre);
    cudaGetSymbolAddress((void**)&pAmax, d_aggmax);
    cudaGetSymbolAddress((void**)&pAmin, d_aggmin);
    cudaGetSymbolAddress((void**)&pSum1, d_colsum1);
    cudaGetSymbolAddress((void**)&pSq1,  d_colsq1);
    cudaGetSymbolAddress((void**)&pSum2, d_colsum2);
    cudaGetSymbolAddress((void**)&pSq2,  d_colsq2);
    cudaGetSymbolAddress((void**)&pSc1,  d_scale1);
    cudaGetSymbolAddress((void**)&pSh1,  d_shift1);
    cudaGetSymbolAddress((void**)&pSc2,  d_scale2);
    cudaGetSymbolAddress((void**)&pSh2,  d_shift2);
    cudaGetSymbolAddress((void**)&pW1h,  d_W1hi);
    cudaGetSymbolAddress((void**)&pW1l,  d_W1lo);
    cudaGetSymbolAddress((void**)&pW2h,  d_W2hi);
    cudaGetSymbolAddress((void**)&pW2l,  d_W2lo);

    cudaFuncSetAttribute(mma_fused<4, 0>, cudaFuncAttributeMaxDynamicSharedMemorySize, GSM_TOTAL);
    cudaFuncSetAttribute(mma_fused<2, 0>, cudaFuncAttributeMaxDynamicSharedMemorySize, GSM_TOTAL);
    cudaFuncSetAttribute(mma_fused<4, 1>, cudaFuncAttributeMaxDynamicSharedMemorySize, GSM_TOTAL);
    cudaFuncSetAttribute(mma_fused<2, 1>, cudaFuncAttributeMaxDynamicSharedMemorySize, GSM_TOTAL);

    const int rows1 = (Nlast + 127) / 128;
    const int rows2 = (Ncur + 127) / 128;

    reset_kernel<<<(Ncur + 255) / 256, 256>>>(Ncur);
    convW_kernel<<<(NPAD * (KPAD / 2) + 255) / 256, 256>>>(W1, 303, pW1h, pW1l);
    convW_kernel<<<(NPAD * (KPAD / 2) + 255) / 256, 256>>>(W2, 300, pW2h, pW2l);
    c2_kernel<<<(Ncur * F_DIM + 255) / 256, 256>>>(current_coors, W1, Ncur);
    count_kernel<<<(E + 255) / 256, 256>>>(cur_idx, E);
    scan_kernel<<<1, 1024>>>(Ncur);
    scatter_kernel<<<(E + 255) / 256, 256>>>(cur_idx, last_idx, E);

    // GEMM1: PC(half) = [feat|coor] @ W1 + b1 (fused fp32->bf16 split conversion)
    mma_fused<4, 0><<<dim3(rows1, 2), 128, GSM_TOTAL>>>(
        last_features, last_coors, pW1h, pW1l, Nlast, 0, nullptr, nullptr, b1, pPC, nullptr, nullptr);
    mma_fused<2, 0><<<dim3(rows1, 1), 128, GSM_TOTAL>>>(
        last_features, last_coors, pW1h, pW1l, Nlast, 256, nullptr, nullptr, b1, pPC, nullptr, nullptr);

    seg_kernel<<<(Ncur + SEGS_PER_BLOCK - 1) / SEGS_PER_BLOCK, 128>>>(Ncur);
    bnparam_kernel<<<(F_DIM + 127) / 128, 128>>>(pSum1, pSq1, 1.0f / (float)E, g1, be1, pSc1, pSh1);

    // GEMM2: ypre = relu(BN1(agg) @ W2 + b2) with fused BN1 apply + BN2 stats
    mma_fused<4, 1><<<dim3(rows2, 2), 128, GSM_TOTAL>>>(
        pAmax, pAmin, pW2h, pW2l, Ncur, 0, pSc1, pSh1, b2, pYpre, pSum2, pSq2);
    mma_fused<2, 1><<<dim3(rows2, 1), 128, GSM_TOTAL>>>(
        pAmax, pAmin, pW2h, pW2l, Ncur, 256, pSc1, pSh1, b2, pYpre, pSum2, pSq2);

    bnparam_kernel<<<(F_DIM + 127) / 128, 128>>>(pSum2, pSq2, 1.0f / (float)Ncur, g2, be2, pSc2, pSh2);
    apply_out_kernel<<<(Ncur * F_DIM + 255) / 256, 256>>>((float*)d_out, Ncur);
}

// round 7
// speedup vs baseline: 1.2564x; 1.2564x over previous
#include <cuda_runtime.h>
#include <cuda_bf16.h>
#include <cstdint>

#define F_DIM 300
#define KPAD 320           // K padded: 5 chunks of 64
#define NPAD 384           // N padded: 3 tiles of 128
#define MAX_NLAST 100000
#define MAX_NCUR  50000
#define MAX_E     500000

// ---------------- scratch (static __device__; no allocation) ----------------
__device__ float d_PC[(size_t)MAX_NLAST * F_DIM];
__device__ float d_c2[(size_t)MAX_NCUR * F_DIM];
__device__ float d_aggmax[(size_t)MAX_NCUR * F_DIM];
__device__ float d_aggmin[(size_t)MAX_NCUR * F_DIM];
__device__ float d_ypre[(size_t)MAX_NCUR * F_DIM];
__device__ __nv_bfloat16 d_A1hi[(size_t)MAX_NLAST * KPAD];
__device__ __nv_bfloat16 d_A1lo[(size_t)MAX_NLAST * KPAD];
__device__ __nv_bfloat16 d_A2hi[(size_t)MAX_NCUR * KPAD];
__device__ __nv_bfloat16 d_A2lo[(size_t)MAX_NCUR * KPAD];
__device__ __nv_bfloat16 d_W1hi[(size_t)NPAD * KPAD];
__device__ __nv_bfloat16 d_W1lo[(size_t)NPAD * KPAD];
__device__ __nv_bfloat16 d_W2hi[(size_t)NPAD * KPAD];
__device__ __nv_bfloat16 d_W2lo[(size_t)NPAD * KPAD];
__device__ int   d_counts[MAX_NCUR];
__device__ int   d_offsets[MAX_NCUR];
__device__ int   d_cursor[MAX_NCUR];
__device__ int   d_edge_l[MAX_E];
__device__ float d_colsum1[F_DIM], d_colsq1[F_DIM];
__device__ float d_colsum2[F_DIM], d_colsq2[F_DIM];
__device__ float d_scale1[F_DIM], d_shift1[F_DIM];
__device__ float d_scale2[F_DIM], d_shift2[F_DIM];

// ---------------- PTX helpers (baseline sm_80+) ----------------
static __device__ __forceinline__ uint32_t smem_u32(const void* p) {
    uint32_t a;
    asm("{ .reg .u64 t; cvta.to.shared.u64 t, %1; cvt.u32.u64 %0, t; }" : "=r"(a) : "l"(p));
    return a;
}
static __device__ __forceinline__ void cp16(uint32_t dst, const void* src, bool pred) {
    int sz = pred ? 16 : 0;
    asm volatile("cp.async.cg.shared.global [%0], [%1], 16, %2;" :: "r"(dst), "l"(src), "r"(sz));
}
#define CP_COMMIT() asm volatile("cp.async.commit_group;" ::: "memory")
#define CP_WAIT(n)  asm volatile("cp.async.wait_group %0;" :: "n"(n) : "memory")

static __device__ __forceinline__ void ldsm_x4(uint32_t* r, uint32_t addr) {
    asm volatile("ldmatrix.sync.aligned.m8n8.x4.shared.b16 {%0,%1,%2,%3}, [%4];"
        : "=r"(r[0]), "=r"(r[1]), "=r"(r[2]), "=r"(r[3]) : "r"(addr));
}
static __device__ __forceinline__ void mma_bf16(float* d, const uint32_t* a, const uint32_t* b) {
    asm volatile("mma.sync.aligned.m16n8k16.row.col.f32.bf16.bf16.f32 "
        "{%0,%1,%2,%3}, {%4,%5,%6,%7}, {%8,%9}, {%0,%1,%2,%3};"
        : "+f"(d[0]), "+f"(d[1]), "+f"(d[2]), "+f"(d[3])
        : "r"(a[0]), "r"(a[1]), "r"(a[2]), "r"(a[3]), "r"(b[0]), "r"(b[1]));
}

// ---------------- tensor-core GEMM: C[M,cols] = A[M,KPAD] @ Wt[NPAD,KPAD]^T + bias ----------
// bf16-split 3 products: Ahi*Bhi + Ahi*Blo + Alo*Bhi. 15 k-chunks of 64.
// NP = n8-pairs per warp: NP=4 -> block covers 128 cols; NP=2 -> 64 cols.
#define BM 128
#define BK 64
#define STAGE_A (BM * BK * 2)             // 16384
#define NCHUNK_TOT 15

template<int NP>
__global__ __launch_bounds__(128, 1)
void mma_gemm(const __nv_bfloat16* __restrict__ Ahi, const __nv_bfloat16* __restrict__ Alo,
              const __nv_bfloat16* __restrict__ Bhi, const __nv_bfloat16* __restrict__ Blo,
              int M, int noff_base,
              const float* __restrict__ bias, float* __restrict__ C, int doRelu)
{
    constexpr int BROWS = NP * 32;                     // B rows per block
    constexpr int STAGE_B = BROWS * 128;               // bytes per B tile (64 bf16/row)
    constexpr int STAGE_BYTES = STAGE_A + STAGE_B;

    extern __shared__ __align__(128) char smem[];
    const uint32_t sb = smem_u32(smem);
    const int tid = threadIdx.x, wid = tid >> 5, lane = tid & 31;
    const int wm = wid & 1, wn = wid >> 1;             // 2x2 warps
    const int m0 = blockIdx.y * BM;
    const int noff = noff_base + blockIdx.x * 128;

    auto load_chunk = [&](int cc, int stage) {
        const int prod = cc / 5;
        const int k0 = (cc - prod * 5) * BK;
        const __nv_bfloat16* Asel = (prod == 2) ? Alo : Ahi;
        const __nv_bfloat16* Bsel = (prod == 1) ? Blo : Bhi;
        const uint32_t abase = sb + stage * STAGE_BYTES;
        const uint32_t bbase = abase + STAGE_A;
#pragma unroll
        for (int i = 0; i < 8; i++) {                   // A: 128 rows x 8 chunks
            int lin = i * 128 + tid;
            int row = lin >> 3, ch = lin & 7;
            bool ok = (m0 + row) < M;
            size_t gr = ok ? (size_t)(m0 + row) : 0;
            cp16(abase + row * 128 + ((ch ^ (row & 7)) * 16),
                 Asel + gr * KPAD + k0 + ch * 8, ok);
        }
#pragma unroll
        for (int i = 0; i < NP * 2; i++) {              // B: BROWS rows x 8 chunks
            int lin = i * 128 + tid;
            int row = lin >> 3, ch = lin & 7;
            cp16(bbase + row * 128 + ((ch ^ (row & 7)) * 16),
                 Bsel + (size_t)(noff + row) * KPAD + k0 + ch * 8, true);
        }
        CP_COMMIT();
    };

    float acc[4][2 * NP][4];
#pragma unroll
    for (int mt = 0; mt < 4; mt++)
#pragma unroll
        for (int nt = 0; nt < 2 * NP; nt++)
#pragma unroll
            for (int q = 0; q < 4; q++) acc[mt][nt][q] = 0.f;

    load_chunk(0, 0);
    load_chunk(1, 1);

    for (int cc = 0; cc < NCHUNK_TOT; cc++) {
        if (cc < NCHUNK_TOT - 1) { CP_WAIT(1); } else { CP_WAIT(0); }
        __syncthreads();
        const uint32_t abase = sb + (cc & 1) * STAGE_BYTES;
        const uint32_t bbase = abase + STAGE_A;
#pragma unroll
        for (int kk = 0; kk < 4; kk++) {
            uint32_t af[4][4], bf[2 * NP][2];
#pragma unroll
            for (int mt = 0; mt < 4; mt++) {
                int row = wm * 64 + mt * 16 + (lane & 15);
                int ch = kk * 2 + (lane >> 4);
                ldsm_x4(af[mt], abase + row * 128 + ((ch ^ (row & 7)) * 16));
            }
#pragma unroll
            for (int np = 0; np < NP; np++) {
                int row = wn * (NP * 16) + np * 16 + ((lane >> 4) << 3) + (lane & 7);
                int ch = kk * 2 + ((lane >> 3) & 1);
                uint32_t r4[4];
                ldsm_x4(r4, bbase + row * 128 + ((ch ^ (row & 7)) * 16));
                bf[np * 2][0] = r4[0]; bf[np * 2][1] = r4[1];
                bf[np * 2 + 1][0] = r4[2]; bf[np * 2 + 1][1] = r4[3];
            }
#pragma unroll
            for (int mt = 0; mt < 4; mt++)
#pragma unroll
                for (int nt = 0; nt < 2 * NP; nt++)
                    mma_bf16(acc[mt][nt], af[mt], bf[nt]);
        }
        __syncthreads();
        if (cc + 2 < NCHUNK_TOT) load_chunk(cc + 2, cc & 1);
    }

    // epilogue: bias (+relu), masked store
    const int g = lane >> 2, t4 = lane & 3;
    const int c0 = noff + wn * (NP * 16);
#pragma unroll
    for (int mt = 0; mt < 4; mt++) {
#pragma unroll
        for (int half = 0; half < 2; half++) {
            const int row = m0 + wm * 64 + mt * 16 + g + half * 8;
            if (row < M) {
                float* crow = C + (size_t)row * F_DIM;
#pragma unroll
                for (int nt = 0; nt < 2 * NP; nt++) {
                    const int col = c0 + nt * 8 + 2 * t4;
                    if (col + 1 < F_DIM) {
                        const float2 bv = *(const float2*)(bias + col);
                        float v0 = acc[mt][nt][half * 2]     + bv.x;
                        float v1 = acc[mt][nt][half * 2 + 1] + bv.y;
                        if (doRelu) { v0 = fmaxf(v0, 0.f); v1 = fmaxf(v1, 0.f); }
                        *(float2*)(crow + col) = make_float2(v0, v1);
                    }
                }
            }
        }
    }
}

// ---------------- conversion kernels ----------------
static __device__ __forceinline__ uint32_t split_pack_hi(float v0, float v1,
                                                         __nv_bfloat16& h0, __nv_bfloat16& h1) {
    h0 = __float2bfloat16(v0); h1 = __float2bfloat16(v1);
    __nv_bfloat162 h = __halves2bfloat162(h0, h1);
    return *(uint32_t*)&h;
}
static __device__ __forceinline__ uint32_t pack_lo(float v0, float v1, __nv_bfloat16 h0, __nv_bfloat16 h1) {
    __nv_bfloat162 l = __floats2bfloat162_rn(v0 - __bfloat162float(h0), v1 - __bfloat162float(h1));
    return *(uint32_t*)&l;
}

__global__ void convA1_kernel(const float* __restrict__ feat, const float* __restrict__ coor, int M) {
    int idx = blockIdx.x * blockDim.x + threadIdx.x;
    if (idx >= M * (KPAD / 2)) return;
    int m = idx / (KPAD / 2), k = (idx % (KPAD / 2)) * 2;
    float v0 = 0.f, v1 = 0.f;
    if (k < F_DIM) v0 = feat[(size_t)m * F_DIM + k];
    else if (k < 303) v0 = coor[(size_t)m * 3 + (k - F_DIM)];
    int k1 = k + 1;
    if (k1 < F_DIM) v1 = feat[(size_t)m * F_DIM + k1];
    else if (k1 < 303) v1 = coor[(size_t)m * 3 + (k1 - F_DIM)];
    __nv_bfloat16 h0, h1;
    uint32_t hp = split_pack_hi(v0, v1, h0, h1);
    uint32_t lp = pack_lo(v0, v1, h0, h1);
    *(uint32_t*)(d_A1hi + (size_t)m * KPAD + k) = hp;
    *(uint32_t*)(d_A1lo + (size_t)m * KPAD + k) = lp;
}

__global__ void convW_kernel(const float* __restrict__ W, int Krows,
                             __nv_bfloat16* __restrict__ hi, __nv_bfloat16* __restrict__ lo) {
    int idx = blockIdx.x * blockDim.x + threadIdx.x;
    if (idx >= NPAD * (KPAD / 2)) return;
    int n = idx / (KPAD / 2), k = (idx % (KPAD / 2)) * 2;
    float v0 = (n < F_DIM && k < Krows) ? W[(size_t)k * F_DIM + n] : 0.f;
    float v1 = (n < F_DIM && k + 1 < Krows) ? W[(size_t)(k + 1) * F_DIM + n] : 0.f;
    __nv_bfloat16 h0, h1;
    uint32_t hp = split_pack_hi(v0, v1, h0, h1);
    uint32_t lp = pack_lo(v0, v1, h0, h1);
    *(uint32_t*)(hi + (size_t)n * KPAD + k) = hp;
    *(uint32_t*)(lo + (size_t)n * KPAD + k) = lp;
}

// BN1 apply on segment max/min, write bf16 split A2 directly
__global__ void apply_agg_conv_kernel(int ncur) {
    int idx = blockIdx.x * blockDim.x + threadIdx.x;
    if (idx >= ncur * (KPAD / 2)) return;
    int rw = idx / (KPAD / 2), k = (idx % (KPAD / 2)) * 2;
    float v0 = 0.f, v1 = 0.f;
    if (k < F_DIM) {
        float m = d_aggmax[(size_t)rw * F_DIM + k];
        if (m >= 0.f) {
            float sc = d_scale1[k];
            float b = (sc >= 0.f) ? m : d_aggmin[(size_t)rw * F_DIM + k];
            v0 = fmaf(b, sc, d_shift1[k]);
        }
    }
    if (k + 1 < F_DIM) {
        float m = d_aggmax[(size_t)rw * F_DIM + k + 1];
        if (m >= 0.f) {
            float sc = d_scale1[k + 1];
            float b = (sc >= 0.f) ? m : d_aggmin[(size_t)rw * F_DIM + k + 1];
            v1 = fmaf(b, sc, d_shift1[k + 1]);
        }
    }
    __nv_bfloat16 h0, h1;
    uint32_t hp = split_pack_hi(v0, v1, h0, h1);
    uint32_t lp = pack_lo(v0, v1, h0, h1);
    *(uint32_t*)(d_A2hi + (size_t)rw * KPAD + k) = hp;
    *(uint32_t*)(d_A2lo + (size_t)rw * KPAD + k) = lp;
}

// ---------------- graph/CSR + misc kernels ----------------
__global__ void reset_kernel(int ncur) {
    int i = blockIdx.x * blockDim.x + threadIdx.x;
    if (i < ncur) d_counts[i] = 0;
    if (i < F_DIM) {
        d_colsum1[i] = 0.f; d_colsq1[i] = 0.f;
        d_colsum2[i] = 0.f; d_colsq2[i] = 0.f;
    }
}

// c2[i, 4c..4c+3] = ccoor[i] . W1[300..302, 4c..4c+3]   (float4 per thread)
__global__ void c2_kernel(const float* __restrict__ ccoors, const float* __restrict__ W1, int ncur) {
    int idx = blockIdx.x * blockDim.x + threadIdx.x;
    if (idx >= ncur * 75) return;
    int i = idx / 75, cg = (idx % 75) * 4;
    float x = ccoors[3 * i], y = ccoors[3 * i + 1], z = ccoors[3 * i + 2];
    const float4 wx = *(const float4*)(W1 + (size_t)300 * F_DIM + cg);
    const float4 wy = *(const float4*)(W1 + (size_t)301 * F_DIM + cg);
    const float4 wz = *(const float4*)(W1 + (size_t)302 * F_DIM + cg);
    float4 r;
    r.x = fmaf(x, wx.x, fmaf(y, wy.x, z * wz.x));
    r.y = fmaf(x, wx.y, fmaf(y, wy.y, z * wz.y));
    r.z = fmaf(x, wx.z, fmaf(y, wy.z, z * wz.z));
    r.w = fmaf(x, wx.w, fmaf(y, wy.w, z * wz.w));
    *(float4*)(d_c2 + (size_t)i * F_DIM + cg) = r;
}

__global__ void count_kernel(const int* __restrict__ cur_idx, int E) {
    int e = blockIdx.x * blockDim.x + threadIdx.x;
    if (e < E) atomicAdd(&d_counts[cur_idx[e]], 1);
}

__global__ void scan_kernel(int n) {
    __shared__ int buf[1024];
    __shared__ int carry_s;
    int tid = threadIdx.x;
    if (tid == 0) carry_s = 0;
    __syncthreads();
    for (int base = 0; base < n; base += 1024) {
        int i = base + tid;
        int x = (i < n) ? d_counts[i] : 0;
        buf[tid] = x;
        __syncthreads();
        for (int off = 1; off < 1024; off <<= 1) {
            int v = (tid >= off) ? buf[tid - off] : 0;
            __syncthreads();
            buf[tid] += v;
            __syncthreads();
        }
        int carry = carry_s;
        int excl = carry + buf[tid] - x;
        if (i < n) { d_offsets[i] = excl; d_cursor[i] = excl; }
        __syncthreads();
        if (tid == 1023) carry_s = carry + buf[1023];
        __syncthreads();
    }
}

__global__ void scatter_kernel(const int* __restrict__ cur_idx, const int* __restrict__ last_idx, int E) {
    int e = blockIdx.x * blockDim.x + threadIdx.x;
    if (e < E) {
        int p = atomicAdd(&d_cursor[cur_idx[e]], 1);
        d_edge_l[p] = last_idx[e];
    }
}

// per-segment max/min of relu(PC[l]-c2[i]) + BN1 stats; float2 vector loads
#define SEGS_PER_BLOCK 4
__global__ __launch_bounds__(128) void seg_kernel(int ncur) {
    const int tid = threadIdx.x;
    const bool h2 = (tid < 22);                 // pairs 128..149 -> cols 256..299
    float2 s0 = {0.f, 0.f}, q0 = {0.f, 0.f}, s1 = {0.f, 0.f}, q1 = {0.f, 0.f};

    int segBeg = blockIdx.x * SEGS_PER_BLOCK;
    int segEnd = min(segBeg + SEGS_PER_BLOCK, ncur);
    for (int seg = segBeg; seg < segEnd; seg++) {
        const float2* c2r = (const float2*)(d_c2 + (size_t)seg * F_DIM);
        float2 cA = c2r[tid];
        float2 cB = h2 ? c2r[128 + tid] : make_float2(0.f, 0.f);
        float2 mxA = {-1.f, -1.f}, mxB = {-1.f, -1.f};
        float2 mnA = {3.4e38f, 3.4e38f}, mnB = {3.4e38f, 3.4e38f};
        int off = d_offsets[seg], cnt = d_counts[seg];
        int t = 0;
        for (; t + 4 <= cnt; t += 4) {
            int l[4];
#pragma unroll
            for (int u = 0; u < 4; u++) l[u] = d_edge_l[off + t + u];
            float2 va[4], vb[4];
#pragma unroll
            for (int u = 0; u < 4; u++) {
                const float2* pr = (const float2*)(d_PC + (size_t)l[u] * F_DIM);
                va[u] = pr[tid];
                vb[u] = h2 ? pr[128 + tid] : make_float2(0.f, 0.f);
            }
#pragma unroll
            for (int u = 0; u < 4; u++) {
                float ax = fmaxf(va[u].x - cA.x, 0.f), ay = fmaxf(va[u].y - cA.y, 0.f);
                float bx = fmaxf(vb[u].x - cB.x, 0.f), by = fmaxf(vb[u].y - cB.y, 0.f);
                s0.x += ax; q0.x += ax * ax; mxA.x = fmaxf(mxA.x, ax); mnA.x = fminf(mnA.x, ax);
                s0.y += ay; q0.y += ay * ay; mxA.y = fmaxf(mxA.y, ay); mnA.y = fminf(mnA.y, ay);
                s1.x += bx; q1.x += bx * bx; mxB.x = fmaxf(mxB.x, bx); mnB.x = fminf(mnB.x, bx);
                s1.y += by; q1.y += by * by; mxB.y = fmaxf(mxB.y, by); mnB.y = fminf(mnB.y, by);
            }
        }
        for (; t < cnt; t++) {
            int lv = d_edge_l[off + t];
            const float2* pr = (const float2*)(d_PC + (size_t)lv * F_DIM);
            float2 va = pr[tid];
            float2 vb = h2 ? pr[128 + tid] : make_float2(0.f, 0.f);
            float ax = fmaxf(va.x - cA.x, 0.f), ay = fmaxf(va.y - cA.y, 0.f);
            float bx = fmaxf(vb.x - cB.x, 0.f), by = fmaxf(vb.y - cB.y, 0.f);
            s0.x += ax; q0.x += ax * ax; mxA.x = fmaxf(mxA.x, ax); mnA.x = fminf(mnA.x, ax);
            s0.y += ay; q0.y += ay * ay; mxA.y = fmaxf(mxA.y, ay); mnA.y = fminf(mnA.y, ay);
            s1.x += bx; q1.x += bx * bx; mxB.x = fmaxf(mxB.x, bx); mnB.x = fminf(mnB.x, bx);
            s1.y += by; q1.y += by * by; mxB.y = fmaxf(mxB.y, by); mnB.y = fminf(mnB.y, by);
        }
        size_t base = (size_t)seg * F_DIM;
        *(float2*)(d_aggmax + base + 2 * tid) = mxA;
        *(float2*)(d_aggmin + base + 2 * tid) = cnt ? mnA : make_float2(0.f, 0.f);
        if (h2) {
            *(float2*)(d_aggmax + base + 256 + 2 * tid) = mxB;
            *(float2*)(d_aggmin + base + 256 + 2 * tid) = cnt ? mnB : make_float2(0.f, 0.f);
        }
    }
    atomicAdd(&d_colsum1[2 * tid], s0.x);     atomicAdd(&d_colsq1[2 * tid], q0.x);
    atomicAdd(&d_colsum1[2 * tid + 1], s0.y); atomicAdd(&d_colsq1[2 * tid + 1], q0.y);
    if (h2) {
        atomicAdd(&d_colsum1[256 + 2 * tid], s1.x); atomicAdd(&d_colsq1[256 + 2 * tid], q1.x);
        atomicAdd(&d_colsum1[257 + 2 * tid], s1.y); atomicAdd(&d_colsq1[257 + 2 * tid], q1.y);
    }
}

__global__ void bnparam_kernel(const float* __restrict__ colsum, const float* __restrict__ colsq,
                               float invN, const float* __restrict__ g, const float* __restrict__ be,
                               float* __restrict__ scale, float* __restrict__ shift) {
    int c = blockIdx.x * blockDim.x + threadIdx.x;
    if (c >= F_DIM) return;
    float mean = colsum[c] * invN;
    float var = colsq[c] * invN - mean * mean;
    if (var < 0.f) var = 0.f;
    float sc = g[c] * rsqrtf(var + 1e-5f);
    scale[c] = sc;
    shift[c] = be[c] - mean * sc;
}

// column stats over ypre [ncur,300]
__global__ void stats2_kernel(int ncur) {
    int col = threadIdx.x;
    if (col >= F_DIM) return;
    float s = 0.f, q = 0.f;
    for (int r = blockIdx.x; r < ncur; r += gridDim.x) {
        float v = d_ypre[(size_t)r * F_DIM + col];
        s += v; q += v * v;
    }
    atomicAdd(&d_colsum2[col], s);
    atomicAdd(&d_colsq2[col], q);
}

__global__ void apply_out_kernel(float* __restrict__ out, int ncur) {
    int idx = blockIdx.x * blockDim.x + threadIdx.x;
    if (idx >= ncur * F_DIM) return;
    int c = idx % F_DIM;
    out[idx] = fmaf(d_ypre[idx], d_scale2[c], d_shift2[c]);
}

// ---------------- launcher ----------------
extern "C" void kernel_launch(void* const* d_in, const int* in_sizes, int n_in,
                              void* d_out, int out_size) {
    const float* last_coors    = (const float*)d_in[0];
    const float* last_features = (const float*)d_in[1];
    const float* current_coors = (const float*)d_in[2];
    const int*   cur_idx       = (const int*)d_in[3];
    const int*   last_idx      = (const int*)d_in[4];
    const float* W1            = (const float*)d_in[5];
    const float* b1            = (const float*)d_in[6];
    const float* g1            = (const float*)d_in[7];
    const float* be1           = (const float*)d_in[8];
    const float* W2            = (const float*)d_in[9];
    const float* b2            = (const float*)d_in[10];
    const float* g2            = (const float*)d_in[11];
    const float* be2           = (const float*)d_in[12];

    const int Nlast = in_sizes[0] / 3;
    const int Ncur  = in_sizes[2] / 3;
    const int E     = in_sizes[3];

    float *pPC, *pYpre, *pSum1, *pSq1, *pSum2, *pSq2, *pSc1, *pSh1, *pSc2, *pSh2;
    __nv_bfloat16 *pA1h, *pA1l, *pA2h, *pA2l, *pW1h, *pW1l, *pW2h, *pW2l;
    cudaGetSymbolAddress((void**)&pPC,   d_PC);
    cudaGetSymbolAddress((void**)&pYpre, d_ypre);
    cudaGetSymbolAddress((void**)&pSum1, d_colsum1);
    cudaGetSymbolAddress((void**)&pSq1,  d_colsq1);
    cudaGetSymbolAddress((void**)&pSum2, d_colsum2);
    cudaGetSymbolAddress((void**)&pSq2,  d_colsq2);
    cudaGetSymbolAddress((void**)&pSc1,  d_scale1);
    cudaGetSymbolAddress((void**)&pSh1,  d_shift1);
    cudaGetSymbolAddress((void**)&pSc2,  d_scale2);
    cudaGetSymbolAddress((void**)&pSh2,  d_shift2);
    cudaGetSymbolAddress((void**)&pA1h,  d_A1hi);
    cudaGetSymbolAddress((void**)&pA1l,  d_A1lo);
    cudaGetSymbolAddress((void**)&pA2h,  d_A2hi);
    cudaGetSymbolAddress((void**)&pA2l,  d_A2lo);
    cudaGetSymbolAddress((void**)&pW1h,  d_W1hi);
    cudaGetSymbolAddress((void**)&pW1l,  d_W1lo);
    cudaGetSymbolAddress((void**)&pW2h,  d_W2hi);
    cudaGetSymbolAddress((void**)&pW2l,  d_W2lo);

    constexpr int SMEM4 = 2 * (STAGE_A + 4 * 32 * 128);  // 65536
    constexpr int SMEM2 = 2 * (STAGE_A + 2 * 32 * 128);  // 49152
    cudaFuncSetAttribute(mma_gemm<4>, cudaFuncAttributeMaxDynamicSharedMemorySize, SMEM4);
    cudaFuncSetAttribute(mma_gemm<2>, cudaFuncAttributeMaxDynamicSharedMemorySize, SMEM2);

    const int rows1 = (Nlast + BM - 1) / BM;
    const int rows2 = (Ncur + BM - 1) / BM;

    reset_kernel<<<(Ncur + 255) / 256, 256>>>(Ncur);
    convW_kernel<<<(NPAD * (KPAD / 2) + 255) / 256, 256>>>(W1, 303, pW1h, pW1l);
    convW_kernel<<<(NPAD * (KPAD / 2) + 255) / 256, 256>>>(W2, 300, pW2h, pW2l);
    convA1_kernel<<<(Nlast * (KPAD / 2) + 255) / 256, 256>>>(last_features, last_coors, Nlast);
    c2_kernel<<<(Ncur * 75 + 255) / 256, 256>>>(current_coors, W1, Ncur);
    count_kernel<<<(E + 255) / 256, 256>>>(cur_idx, E);
    scan_kernel<<<1, 1024>>>(Ncur);
    scatter_kernel<<<(E + 255) / 256, 256>>>(cur_idx, last_idx, E);

    // GEMM1: PC = [feat|coor] @ W1 + b1   (cols 0..255 with NP=4, cols 256..299 with NP=2)
    mma_gemm<4><<<dim3(2, rows1), 128, SMEM4>>>(pA1h, pA1l, pW1h, pW1l, Nlast, 0, b1, pPC, 0);
    mma_gemm<2><<<dim3(1, rows1), 128, SMEM2>>>(pA1h, pA1l, pW1h, pW1l, Nlast, 256, b1, pPC, 0);

    seg_kernel<<<(Ncur + SEGS_PER_BLOCK - 1) / SEGS_PER_BLOCK, 128>>>(Ncur);
    bnparam_kernel<<<(F_DIM + 127) / 128, 128>>>(pSum1, pSq1, 1.0f / (float)E, g1, be1, pSc1, pSh1);
    apply_agg_conv_kernel<<<(Ncur * (KPAD / 2) + 255) / 256, 256>>>(Ncur);

    // GEMM2: ypre = relu(agg @ W2 + b2)
    mma_gemm<4><<<dim3(2, rows2), 128, SMEM4>>>(pA2h, pA2l, pW2h, pW2l, Ncur, 0, b2, pYpre, 1);
    mma_gemm<2><<<dim3(1, rows2), 128, SMEM2>>>(pA2h, pA2l, pW2h, pW2l, Ncur, 256, b2, pYpre, 1);

    stats2_kernel<<<256, 320>>>(Ncur);
    bnparam_kernel<<<(F_DIM + 127) / 128, 128>>>(pSum2, pSq2, 1.0f / (float)Ncur, g2, be2, pSc2, pSh2);
    apply_out_kernel<<<(Ncur * F_DIM + 255) / 256, 256>>>((float*)d_out, Ncur);
}

// round 8
// speedup vs baseline: 1.3069x; 1.0402x over previous
#include <cuda_runtime.h>
#include <cuda_bf16.h>
#include <cstdint>

#define F_DIM 300
#define KPAD 320           // K padded: 5 chunks of 64
#define NPAD 384           // N padded: 3 tiles of 128
#define MAX_NLAST 100000
#define MAX_NCUR  50000
#define MAX_E     500000

// ---------------- scratch (static __device__; no allocation) ----------------
__device__ float d_PC[(size_t)MAX_NLAST * F_DIM];
__device__ float d_c2[(size_t)MAX_NCUR * F_DIM];
__device__ float d_aggmax[(size_t)MAX_NCUR * F_DIM];
__device__ float d_aggmin[(size_t)MAX_NCUR * F_DIM];
__device__ float d_ypre[(size_t)MAX_NCUR * F_DIM];
__device__ __nv_bfloat16 d_A1hi[(size_t)MAX_NLAST * KPAD];
__device__ __nv_bfloat16 d_A1lo[(size_t)MAX_NLAST * KPAD];
__device__ __nv_bfloat16 d_A2hi[(size_t)MAX_NCUR * KPAD];
__device__ __nv_bfloat16 d_A2lo[(size_t)MAX_NCUR * KPAD];
__device__ __nv_bfloat16 d_W1hi[(size_t)NPAD * KPAD];
__device__ __nv_bfloat16 d_W1lo[(size_t)NPAD * KPAD];
__device__ __nv_bfloat16 d_W2hi[(size_t)NPAD * KPAD];
__device__ __nv_bfloat16 d_W2lo[(size_t)NPAD * KPAD];
__device__ int   d_counts[MAX_NCUR];
__device__ int   d_offsets[MAX_NCUR];
__device__ int   d_cursor[MAX_NCUR];
__device__ int   d_edge_l[MAX_E];
__device__ float d_colsum1[F_DIM], d_colsq1[F_DIM];
__device__ float d_colsum2[F_DIM], d_colsq2[F_DIM];
__device__ float d_scale1[F_DIM], d_shift1[F_DIM];
__device__ float d_scale2[F_DIM], d_shift2[F_DIM];

// ---------------- PTX helpers (baseline sm_80+) ----------------
static __device__ __forceinline__ uint32_t smem_u32(const void* p) {
    uint32_t a;
    asm("{ .reg .u64 t; cvta.to.shared.u64 t, %1; cvt.u32.u64 %0, t; }" : "=r"(a) : "l"(p));
    return a;
}
static __device__ __forceinline__ void cp16(uint32_t dst, const void* src, bool pred) {
    int sz = pred ? 16 : 0;
    asm volatile("cp.async.cg.shared.global [%0], [%1], 16, %2;" :: "r"(dst), "l"(src), "r"(sz));
}
#define CP_COMMIT() asm volatile("cp.async.commit_group;" ::: "memory")
#define CP_WAIT(n)  asm volatile("cp.async.wait_group %0;" :: "n"(n) : "memory")

static __device__ __forceinline__ void ldsm_x4(uint32_t* r, uint32_t addr) {
    asm volatile("ldmatrix.sync.aligned.m8n8.x4.shared.b16 {%0,%1,%2,%3}, [%4];"
        : "=r"(r[0]), "=r"(r[1]), "=r"(r[2]), "=r"(r[3]) : "r"(addr));
}
static __device__ __forceinline__ void mma_bf16(float* d, const uint32_t* a, const uint32_t* b) {
    asm volatile("mma.sync.aligned.m16n8k16.row.col.f32.bf16.bf16.f32 "
        "{%0,%1,%2,%3}, {%4,%5,%6,%7}, {%8,%9}, {%0,%1,%2,%3};"
        : "+f"(d[0]), "+f"(d[1]), "+f"(d[2]), "+f"(d[3])
        : "r"(a[0]), "r"(a[1]), "r"(a[2]), "r"(a[3]), "r"(b[0]), "r"(b[1]));
}

// ---------------- tensor-core GEMM: C[M,300] = A[M,KPAD] @ Wt[NPAD,KPAD]^T + bias ----------------
// bf16-split 3 products: Ahi*Bhi + Ahi*Blo + Alo*Bhi. 15 k-chunks of 64.
// Single launch, grid (3, rowTiles): uniform 128-col n-tiles (zero-padded W).
// Optional fused per-column stats (colsum/colsq) for BN2.
#define BM 128
#define BN 128
#define BK 64
#define STAGE_A (BM * BK * 2)             // 16384
#define STAGE_B (BN * BK * 2)             // 16384
#define STAGE_BYTES (STAGE_A + STAGE_B)   // 32768
#define GEMM_SMEM (2 * STAGE_BYTES)       // 65536
#define NCHUNK_TOT 15

__global__ __launch_bounds__(128, 1)
void mma_gemm(const __nv_bfloat16* __restrict__ Ahi, const __nv_bfloat16* __restrict__ Alo,
              const __nv_bfloat16* __restrict__ Bhi, const __nv_bfloat16* __restrict__ Blo,
              int M, const float* __restrict__ bias, float* __restrict__ C, int doRelu,
              float* __restrict__ colsum, float* __restrict__ colsq)
{
    extern __shared__ __align__(128) char smem[];
    const uint32_t sb = smem_u32(smem);
    const int tid = threadIdx.x, wid = tid >> 5, lane = tid & 31;
    const int wm = wid & 1, wn = wid >> 1;          // 2x2 warps, 64x64 tiles
    const int m0 = blockIdx.y * BM;
    const int nb = blockIdx.x;                      // 0..2

    auto load_chunk = [&](int cc, int stage) {
        const int prod = cc / 5;
        const int k0 = (cc - prod * 5) * BK;
        const __nv_bfloat16* Asel = (prod == 2) ? Alo : Ahi;
        const __nv_bfloat16* Bsel = (prod == 1) ? Blo : Bhi;
        const uint32_t abase = sb + stage * STAGE_BYTES;
        const uint32_t bbase = abase + STAGE_A;
#pragma unroll
        for (int i = 0; i < 8; i++) {                   // A: 128 rows x 8 chunks
            int lin = i * 128 + tid;
            int row = lin >> 3, ch = lin & 7;
            bool ok = (m0 + row) < M;
            size_t gr = ok ? (size_t)(m0 + row) : 0;
            cp16(abase + row * 128 + ((ch ^ (row & 7)) * 16),
                 Asel + gr * KPAD + k0 + ch * 8, ok);
        }
#pragma unroll
        for (int i = 0; i < 8; i++) {                   // B: 128 rows x 8 chunks
            int lin = i * 128 + tid;
            int row = lin >> 3, ch = lin & 7;
            cp16(bbase + row * 128 + ((ch ^ (row & 7)) * 16),
                 Bsel + (size_t)(nb * 128 + row) * KPAD + k0 + ch * 8, true);
        }
        CP_COMMIT();
    };

    float acc[4][8][4];
#pragma unroll
    for (int mt = 0; mt < 4; mt++)
#pragma unroll
        for (int nt = 0; nt < 8; nt++)
#pragma unroll
            for (int q = 0; q < 4; q++) acc[mt][nt][q] = 0.f;

    load_chunk(0, 0);
    load_chunk(1, 1);

    for (int cc = 0; cc < NCHUNK_TOT; cc++) {
        if (cc < NCHUNK_TOT - 1) { CP_WAIT(1); } else { CP_WAIT(0); }
        __syncthreads();
        const uint32_t abase = sb + (cc & 1) * STAGE_BYTES;
        const uint32_t bbase = abase + STAGE_A;
#pragma unroll
        for (int kk = 0; kk < 4; kk++) {
            uint32_t af[4][4], bf[8][2];
#pragma unroll
            for (int mt = 0; mt < 4; mt++) {
                int row = wm * 64 + mt * 16 + (lane & 15);
                int ch = kk * 2 + (lane >> 4);
                ldsm_x4(af[mt], abase + row * 128 + ((ch ^ (row & 7)) * 16));
            }
#pragma unroll
            for (int np = 0; np < 4; np++) {            // pairs of n8 tiles via x4
                int row = wn * 64 + np * 16 + ((lane >> 4) << 3) + (lane & 7);
                int ch = kk * 2 + ((lane >> 3) & 1);
                uint32_t r4[4];
                ldsm_x4(r4, bbase + row * 128 + ((ch ^ (row & 7)) * 16));
                bf[np * 2][0] = r4[0]; bf[np * 2][1] = r4[1];
                bf[np * 2 + 1][0] = r4[2]; bf[np * 2 + 1][1] = r4[3];
            }
#pragma unroll
            for (int mt = 0; mt < 4; mt++)
#pragma unroll
                for (int nt = 0; nt < 8; nt++)
                    mma_bf16(acc[mt][nt], af[mt], bf[nt]);
        }
        __syncthreads();
        if (cc + 2 < NCHUNK_TOT) load_chunk(cc + 2, cc & 1);
    }

    // epilogue: bias (+relu), masked store, optional column stats
    const int g = lane >> 2, t4 = lane & 3;
    const int c0 = nb * 128 + wn * 64;
    float cs[8][2], cq[8][2];
#pragma unroll
    for (int nt = 0; nt < 8; nt++) { cs[nt][0] = cs[nt][1] = 0.f; cq[nt][0] = cq[nt][1] = 0.f; }

#pragma unroll
    for (int mt = 0; mt < 4; mt++) {
#pragma unroll
        for (int half = 0; half < 2; half++) {
            const int row = m0 + wm * 64 + mt * 16 + g + half * 8;
            if (row < M) {
                float* crow = C + (size_t)row * F_DIM;
#pragma unroll
                for (int nt = 0; nt < 8; nt++) {
                    const int col = c0 + nt * 8 + 2 * t4;
                    if (col + 1 < F_DIM) {
                        const float2 bv = *(const float2*)(bias + col);
                        float v0 = acc[mt][nt][half * 2]     + bv.x;
                        float v1 = acc[mt][nt][half * 2 + 1] + bv.y;
                        if (doRelu) { v0 = fmaxf(v0, 0.f); v1 = fmaxf(v1, 0.f); }
                        *(float2*)(crow + col) = make_float2(v0, v1);
                        cs[nt][0] += v0; cq[nt][0] += v0 * v0;
                        cs[nt][1] += v1; cq[nt][1] += v1 * v1;
                    }
                }
            }
        }
    }

    if (colsum) {
        float* redS = (float*)smem;           // 128 floats
        float* redQ = (float*)smem + 128;     // 128 floats
        __syncthreads();
        redS[tid] = 0.f; redQ[tid] = 0.f;
        __syncthreads();
#pragma unroll
        for (int nt = 0; nt < 8; nt++) {
            int lc = wn * 64 + nt * 8 + 2 * t4;      // local col 0..127
            atomicAdd(&redS[lc], cs[nt][0]);     atomicAdd(&redQ[lc], cq[nt][0]);
            atomicAdd(&redS[lc + 1], cs[nt][1]); atomicAdd(&redQ[lc + 1], cq[nt][1]);
        }
        __syncthreads();
        int col = nb * 128 + tid;
        if (col < F_DIM) {
            atomicAdd(colsum + col, redS[tid]);
            atomicAdd(colsq + col, redQ[tid]);
        }
    }
}

// ---------------- conversion kernels ----------------
static __device__ __forceinline__ uint32_t split_pack_hi(float v0, float v1,
                                                         __nv_bfloat16& h0, __nv_bfloat16& h1) {
    h0 = __float2bfloat16(v0); h1 = __float2bfloat16(v1);
    __nv_bfloat162 h = __halves2bfloat162(h0, h1);
    return *(uint32_t*)&h;
}
static __device__ __forceinline__ uint32_t pack_lo(float v0, float v1, __nv_bfloat16 h0, __nv_bfloat16 h1) {
    __nv_bfloat162 l = __floats2bfloat162_rn(v0 - __bfloat162float(h0), v1 - __bfloat162float(h1));
    return *(uint32_t*)&l;
}

__global__ void convA1_kernel(const float* __restrict__ feat, const float* __restrict__ coor, int M) {
    int idx = blockIdx.x * blockDim.x + threadIdx.x;
    if (idx >= M * (KPAD / 2)) return;
    int m = idx / (KPAD / 2), k = (idx % (KPAD / 2)) * 2;
    float v0 = 0.f, v1 = 0.f;
    if (k < F_DIM) v0 = feat[(size_t)m * F_DIM + k];
    else if (k < 303) v0 = coor[(size_t)m * 3 + (k - F_DIM)];
    int k1 = k + 1;
    if (k1 < F_DIM) v1 = feat[(size_t)m * F_DIM + k1];
    else if (k1 < 303) v1 = coor[(size_t)m * 3 + (k1 - F_DIM)];
    __nv_bfloat16 h0, h1;
    uint32_t hp = split_pack_hi(v0, v1, h0, h1);
    uint32_t lp = pack_lo(v0, v1, h0, h1);
    *(uint32_t*)(d_A1hi + (size_t)m * KPAD + k) = hp;
    *(uint32_t*)(d_A1lo + (size_t)m * KPAD + k) = lp;
}

__global__ void convW_kernel(const float* __restrict__ W, int Krows,
                             __nv_bfloat16* __restrict__ hi, __nv_bfloat16* __restrict__ lo) {
    int idx = blockIdx.x * blockDim.x + threadIdx.x;
    if (idx >= NPAD * (KPAD / 2)) return;
    int n = idx / (KPAD / 2), k = (idx % (KPAD / 2)) * 2;
    float v0 = (n < F_DIM && k < Krows) ? W[(size_t)k * F_DIM + n] : 0.f;
    float v1 = (n < F_DIM && k + 1 < Krows) ? W[(size_t)(k + 1) * F_DIM + n] : 0.f;
    __nv_bfloat16 h0, h1;
    uint32_t hp = split_pack_hi(v0, v1, h0, h1);
    uint32_t lp = pack_lo(v0, v1, h0, h1);
    *(uint32_t*)(hi + (size_t)n * KPAD + k) = hp;
    *(uint32_t*)(lo + (size_t)n * KPAD + k) = lp;
}

// BN1 apply on segment max/min, write bf16 split A2 directly
__global__ void apply_agg_conv_kernel(int ncur) {
    int idx = blockIdx.x * blockDim.x + threadIdx.x;
    if (idx >= ncur * (KPAD / 2)) return;
    int rw = idx / (KPAD / 2), k = (idx % (KPAD / 2)) * 2;
    float v0 = 0.f, v1 = 0.f;
    if (k < F_DIM) {
        float m = d_aggmax[(size_t)rw * F_DIM + k];
        if (m >= 0.f) {
            float sc = d_scale1[k];
            float b = (sc >= 0.f) ? m : d_aggmin[(size_t)rw * F_DIM + k];
            v0 = fmaf(b, sc, d_shift1[k]);
        }
    }
    if (k + 1 < F_DIM) {
        float m = d_aggmax[(size_t)rw * F_DIM + k + 1];
        if (m >= 0.f) {
            float sc = d_scale1[k + 1];
            float b = (sc >= 0.f) ? m : d_aggmin[(size_t)rw * F_DIM + k + 1];
            v1 = fmaf(b, sc, d_shift1[k + 1]);
        }
    }
    __nv_bfloat16 h0, h1;
    uint32_t hp = split_pack_hi(v0, v1, h0, h1);
    uint32_t lp = pack_lo(v0, v1, h0, h1);
    *(uint32_t*)(d_A2hi + (size_t)rw * KPAD + k) = hp;
    *(uint32_t*)(d_A2lo + (size_t)rw * KPAD + k) = lp;
}

// ---------------- graph/CSR + misc kernels ----------------
__global__ void reset_kernel(int ncur) {
    int i = blockIdx.x * blockDim.x + threadIdx.x;
    if (i < ncur) d_counts[i] = 0;
    if (i < F_DIM) {
        d_colsum1[i] = 0.f; d_colsq1[i] = 0.f;
        d_colsum2[i] = 0.f; d_colsq2[i] = 0.f;
    }
}

// c2[i, 4c..4c+3] = ccoor[i] . W1[300..302, 4c..4c+3]   (float4 per thread)
__global__ void c2_kernel(const float* __restrict__ ccoors, const float* __restrict__ W1, int ncur) {
    int idx = blockIdx.x * blockDim.x + threadIdx.x;
    if (idx >= ncur * 75) return;
    int i = idx / 75, cg = (idx % 75) * 4;
    float x = ccoors[3 * i], y = ccoors[3 * i + 1], z = ccoors[3 * i + 2];
    const float4 wx = *(const float4*)(W1 + (size_t)300 * F_DIM + cg);
    const float4 wy = *(const float4*)(W1 + (size_t)301 * F_DIM + cg);
    const float4 wz = *(const float4*)(W1 + (size_t)302 * F_DIM + cg);
    float4 r;
    r.x = fmaf(x, wx.x, fmaf(y, wy.x, z * wz.x));
    r.y = fmaf(x, wx.y, fmaf(y, wy.y, z * wz.y));
    r.z = fmaf(x, wx.z, fmaf(y, wy.z, z * wz.z));
    r.w = fmaf(x, wx.w, fmaf(y, wy.w, z * wz.w));
    *(float4*)(d_c2 + (size_t)i * F_DIM + cg) = r;
}

__global__ void count_kernel(const int* __restrict__ cur_idx, int E) {
    int e = blockIdx.x * blockDim.x + threadIdx.x;
    if (e < E) atomicAdd(&d_counts[cur_idx[e]], 1);
}

__global__ void scan_kernel(int n) {
    __shared__ int buf[1024];
    __shared__ int carry_s;
    int tid = threadIdx.x;
    if (tid == 0) carry_s = 0;
    __syncthreads();
    for (int base = 0; base < n; base += 1024) {
        int i = base + tid;
        int x = (i < n) ? d_counts[i] : 0;
        buf[tid] = x;
        __syncthreads();
        for (int off = 1; off < 1024; off <<= 1) {
            int v = (tid >= off) ? buf[tid - off] : 0;
            __syncthreads();
            buf[tid] += v;
            __syncthreads();
        }
        int carry = carry_s;
        int excl = carry + buf[tid] - x;
        if (i < n) { d_offsets[i] = excl; d_cursor[i] = excl; }
        __syncthreads();
        if (tid == 1023) carry_s = carry + buf[1023];
        __syncthreads();
    }
}

__global__ void scatter_kernel(const int* __restrict__ cur_idx, const int* __restrict__ last_idx, int E) {
    int e = blockIdx.x * blockDim.x + threadIdx.x;
    if (e < E) {
        int p = atomicAdd(&d_cursor[cur_idx[e]], 1);
        d_edge_l[p] = last_idx[e];
    }
}

// per-segment max/min of relu(PC[l]-c2[i]) + BN1 stats; float2 vector loads
#define SEGS_PER_BLOCK 4
__global__ __launch_bounds__(128) void seg_kernel(int ncur) {
    const int tid = threadIdx.x;
    const bool h2 = (tid < 22);                 // pairs 128..149 -> cols 256..299
    float2 s0 = {0.f, 0.f}, q0 = {0.f, 0.f}, s1 = {0.f, 0.f}, q1 = {0.f, 0.f};

    int segBeg = blockIdx.x * SEGS_PER_BLOCK;
    int segEnd = min(segBeg + SEGS_PER_BLOCK, ncur);
    for (int seg = segBeg; seg < segEnd; seg++) {
        const float2* c2r = (const float2*)(d_c2 + (size_t)seg * F_DIM);
        float2 cA = c2r[tid];
        float2 cB = h2 ? c2r[128 + tid] : make_float2(0.f, 0.f);
        float2 mxA = {-1.f, -1.f}, mxB = {-1.f, -1.f};
        float2 mnA = {3.4e38f, 3.4e38f}, mnB = {3.4e38f, 3.4e38f};
        int off = d_offsets[seg], cnt = d_counts[seg];
        int t = 0;
        for (; t + 4 <= cnt; t += 4) {
            int l[4];
#pragma unroll
            for (int u = 0; u < 4; u++) l[u] = d_edge_l[off + t + u];
            float2 va[4], vb[4];
#pragma unroll
            for (int u = 0; u < 4; u++) {
                const float2* pr = (const float2*)(d_PC + (size_t)l[u] * F_DIM);
                va[u] = pr[tid];
                vb[u] = h2 ? pr[128 + tid] : make_float2(0.f, 0.f);
            }
#pragma unroll
            for (int u = 0; u < 4; u++) {
                float ax = fmaxf(va[u].x - cA.x, 0.f), ay = fmaxf(va[u].y - cA.y, 0.f);
                float bx = fmaxf(vb[u].x - cB.x, 0.f), by = fmaxf(vb[u].y - cB.y, 0.f);
                s0.x += ax; q0.x += ax * ax; mxA.x = fmaxf(mxA.x, ax); mnA.x = fminf(mnA.x, ax);
                s0.y += ay; q0.y += ay * ay; mxA.y = fmaxf(mxA.y, ay); mnA.y = fminf(mnA.y, ay);
                s1.x += bx; q1.x += bx * bx; mxB.x = fmaxf(mxB.x, bx); mnB.x = fminf(mnB.x, bx);
                s1.y += by; q1.y += by * by; mxB.y = fmaxf(mxB.y, by); mnB.y = fminf(mnB.y, by);
            }
        }
        for (; t < cnt; t++) {
            int lv = d_edge_l[off + t];
            const float2* pr = (const float2*)(d_PC + (size_t)lv * F_DIM);
            float2 va = pr[tid];
            float2 vb = h2 ? pr[128 + tid] : make_float2(0.f, 0.f);
            float ax = fmaxf(va.x - cA.x, 0.f), ay = fmaxf(va.y - cA.y, 0.f);
            float bx = fmaxf(vb.x - cB.x, 0.f), by = fmaxf(vb.y - cB.y, 0.f);
            s0.x += ax; q0.x += ax * ax; mxA.x = fmaxf(mxA.x, ax); mnA.x = fminf(mnA.x, ax);
            s0.y += ay; q0.y += ay * ay; mxA.y = fmaxf(mxA.y, ay); mnA.y = fminf(mnA.y, ay);
            s1.x += bx; q1.x += bx * bx; mxB.x = fmaxf(mxB.x, bx); mnB.x = fminf(mnB.x, bx);
            s1.y += by; q1.y += by * by; mxB.y = fmaxf(mxB.y, by); mnB.y = fminf(mnB.y, by);
        }
        size_t base = (size_t)seg * F_DIM;
        *(float2*)(d_aggmax + base + 2 * tid) = mxA;
        *(float2*)(d_aggmin + base + 2 * tid) = cnt ? mnA : make_float2(0.f, 0.f);
        if (h2) {
            *(float2*)(d_aggmax + base + 256 + 2 * tid) = mxB;
            *(float2*)(d_aggmin + base + 256 + 2 * tid) = cnt ? mnB : make_float2(0.f, 0.f);
        }
    }
    atomicAdd(&d_colsum1[2 * tid], s0.x);     atomicAdd(&d_colsq1[2 * tid], q0.x);
    atomicAdd(&d_colsum1[2 * tid + 1], s0.y); atomicAdd(&d_colsq1[2 * tid + 1], q0.y);
    if (h2) {
        atomicAdd(&d_colsum1[256 + 2 * tid], s1.x); atomicAdd(&d_colsq1[256 + 2 * tid], q1.x);
        atomicAdd(&d_colsum1[257 + 2 * tid], s1.y); atomicAdd(&d_colsq1[257 + 2 * tid], q1.y);
    }
}

__global__ void bnparam_kernel(const float* __restrict__ colsum, const float* __restrict__ colsq,
                               float invN, const float* __restrict__ g, const float* __restrict__ be,
                               float* __restrict__ scale, float* __restrict__ shift) {
    int c = blockIdx.x * blockDim.x + threadIdx.x;
    if (c >= F_DIM) return;
    float mean = colsum[c] * invN;
    float var = colsq[c] * invN - mean * mean;
    if (var < 0.f) var = 0.f;
    float sc = g[c] * rsqrtf(var + 1e-5f);
    scale[c] = sc;
    shift[c] = be[c] - mean * sc;
}

__global__ void apply_out_kernel(float* __restrict__ out, int ncur) {
    int idx = blockIdx.x * blockDim.x + threadIdx.x;
    if (idx >= ncur * F_DIM) return;
    int c = idx % F_DIM;
    out[idx] = fmaf(d_ypre[idx], d_scale2[c], d_shift2[c]);
}

// ---------------- launcher ----------------
extern "C" void kernel_launch(void* const* d_in, const int* in_sizes, int n_in,
                              void* d_out, int out_size) {
    const float* last_coors    = (const float*)d_in[0];
    const float* last_features = (const float*)d_in[1];
    const float* current_coors = (const float*)d_in[2];
    const int*   cur_idx       = (const int*)d_in[3];
    const int*   last_idx      = (const int*)d_in[4];
    const float* W1            = (const float*)d_in[5];
    const float* b1            = (const float*)d_in[6];
    const float* g1            = (const float*)d_in[7];
    const float* be1           = (const float*)d_in[8];
    const float* W2            = (const float*)d_in[9];
    const float* b2            = (const float*)d_in[10];
    const float* g2            = (const float*)d_in[11];
    const float* be2           = (const float*)d_in[12];

    const int Nlast = in_sizes[0] / 3;
    const int Ncur  = in_sizes[2] / 3;
    const int E     = in_sizes[3];

    float *pPC, *pYpre, *pSum1, *pSq1, *pSum2, *pSq2, *pSc1, *pSh1, *pSc2, *pSh2;
    __nv_bfloat16 *pA1h, *pA1l, *pA2h, *pA2l, *pW1h, *pW1l, *pW2h, *pW2l;
    cudaGetSymbolAddress((void**)&pPC,   d_PC);
    cudaGetSymbolAddress((void**)&pYpre, d_ypre);
    cudaGetSymbolAddress((void**)&pSum1, d_colsum1);
    cudaGetSymbolAddress((void**)&pSq1,  d_colsq1);
    cudaGetSymbolAddress((void**)&pSum2, d_colsum2);
    cudaGetSymbolAddress((void**)&pSq2,  d_colsq2);
    cudaGetSymbolAddress((void**)&pSc1,  d_scale1);
    cudaGetSymbolAddress((void**)&pSh1,  d_shift1);
    cudaGetSymbolAddress((void**)&pSc2,  d_scale2);
    cudaGetSymbolAddress((void**)&pSh2,  d_shift2);
    cudaGetSymbolAddress((void**)&pA1h,  d_A1hi);
    cudaGetSymbolAddress((void**)&pA1l,  d_A1lo);
    cudaGetSymbolAddress((void**)&pA2h,  d_A2hi);
    cudaGetSymbolAddress((void**)&pA2l,  d_A2lo);
    cudaGetSymbolAddress((void**)&pW1h,  d_W1hi);
    cudaGetSymbolAddress((void**)&pW1l,  d_W1lo);
    cudaGetSymbolAddress((void**)&pW2h,  d_W2hi);
    cudaGetSymbolAddress((void**)&pW2l,  d_W2lo);

    cudaFuncSetAttribute(mma_gemm, cudaFuncAttributeMaxDynamicSharedMemorySize, GEMM_SMEM);

    const int rows1 = (Nlast + BM - 1) / BM;
    const int rows2 = (Ncur + BM - 1) / BM;

    reset_kernel<<<(Ncur + 255) / 256, 256>>>(Ncur);
    convW_kernel<<<(NPAD * (KPAD / 2) + 255) / 256, 256>>>(W1, 303, pW1h, pW1l);
    convW_kernel<<<(NPAD * (KPAD / 2) + 255) / 256, 256>>>(W2, 300, pW2h, pW2l);
    convA1_kernel<<<(Nlast * (KPAD / 2) + 255) / 256, 256>>>(last_features, last_coors, Nlast);
    c2_kernel<<<(Ncur * 75 + 255) / 256, 256>>>(current_coors, W1, Ncur);
    count_kernel<<<(E + 255) / 256, 256>>>(cur_idx, E);
    scan_kernel<<<1, 1024>>>(Ncur);
    scatter_kernel<<<(E + 255) / 256, 256>>>(cur_idx, last_idx, E);

    // GEMM1: PC = [feat|coor] @ W1 + b1   (single launch, 3 uniform n-tiles)
    mma_gemm<<<dim3(3, rows1), 128, GEMM_SMEM>>>(
        pA1h, pA1l, pW1h, pW1l, Nlast, b1, pPC, 0, nullptr, nullptr);

    seg_kernel<<<(Ncur + SEGS_PER_BLOCK - 1) / SEGS_PER_BLOCK, 128>>>(Ncur);
    bnparam_kernel<<<(F_DIM + 127) / 128, 128>>>(pSum1, pSq1, 1.0f / (float)E, g1, be1, pSc1, pSh1);
    apply_agg_conv_kernel<<<(Ncur * (KPAD / 2) + 255) / 256, 256>>>(Ncur);

    // GEMM2: ypre = relu(agg @ W2 + b2) with fused BN2 stats
    mma_gemm<<<dim3(3, rows2), 128, GEMM_SMEM>>>(
        pA2h, pA2l, pW2h, pW2l, Ncur, b2, pYpre, 1, pSum2, pSq2);

    bnparam_kernel<<<(F_DIM + 127) / 128, 128>>>(pSum2, pSq2, 1.0f / (float)Ncur, g2, be2, pSc2, pSh2);
    apply_out_kernel<<<(Ncur * F_DIM + 255) / 256, 256>>>((float*)d_out, Ncur);
}